// round 2
// baseline (speedup 1.0000x reference)
#include <cuda_runtime.h>
#include <cuda_fp16.h>
#include <mma.h>

using namespace nvcuda;

#define B_    1024
#define T_    128
#define H_    512
#define RNNIN 128
#define LENV  1500
#define IPDV  256
#define EB    64
#define LAB   100

// recurrence tiling
#define MB   32      // batch rows per cluster
#define NN   128     // hidden slice per CTA
#define LDW  136     // sW row pitch (halves)
#define LDH  520     // sH row pitch (halves)
#define LDA  132     // sAcc row pitch (floats)
#define SMEM_BYTES (H_*LDW*2 + MB*LDH*2 + MB*LDA*4)   // 139264+33280+16896 = 189440

// ---------------- device scratch (static: no allocation allowed) ----------------
__device__ float  g_Wc[H_ * RNNIN];         // x2h_w @ fc1_w  [512,128]
__device__ float  g_c[H_];                  // folded bias (x2h_w@fc1_b + x2h_b + h2h_b)
__device__ float  g_Alen[LENV * H_];        // fused len table [1500,512] (includes g_c)
__device__ float  g_Aipd[IPDV * H_];        // fused ipd table [256,512]
__device__ __half g_W16t[H_ * H_];          // h2h_w transposed to [k][n], fp16
__device__ __half g_h16[2][B_ * H_];        // double-buffered recurrent state (fp16)
__device__ float  g_hlast[B_ * H_];         // final state in fp32 for fc2

// ---------------- kernel A: Wc = x2h_w @ fc1_w ; folded bias ----------------
__global__ void k_prep(const float* __restrict__ fc1_w, const float* __restrict__ fc1_b,
                       const float* __restrict__ x2h_w, const float* __restrict__ x2h_b,
                       const float* __restrict__ h2h_b) {
    __shared__ float s[RNNIN];
    int n = blockIdx.x;          // 0..511
    int f = threadIdx.x;         // 0..127
    s[f] = x2h_w[n * RNNIN + f];
    __syncthreads();
    float acc = 0.f;
#pragma unroll 4
    for (int j = 0; j < RNNIN; ++j) acc += s[j] * fc1_w[j * 128 + f];
    g_Wc[n * RNNIN + f] = acc;
    if (f == 0) {
        float cb = x2h_b[n] + h2h_b[n];
        for (int j = 0; j < RNNIN; ++j) cb += s[j] * fc1_b[j];
        g_c[n] = cb;
    }
}

// ---------------- kernel B: fused embedding tables ----------------
#define RPB 16
__global__ void k_tables(const float* __restrict__ len_emb, const float* __restrict__ ipd_emb) {
    __shared__ float se[RPB][EB];
    int bid = blockIdx.x;
    const int lenBlocks = (LENV + RPB - 1) / RPB;   // 94
    bool isLen = bid < lenBlocks;
    int rbase, nrows, koff;
    const float* emb;
    float* dst;
    if (isLen) { rbase = bid * RPB;              nrows = LENV; koff = 0;  emb = len_emb; dst = g_Alen; }
    else       { rbase = (bid - lenBlocks) * RPB; nrows = IPDV; koff = EB; emb = ipd_emb; dst = g_Aipd; }

    for (int i = threadIdx.x; i < RPB * EB; i += blockDim.x) {
        int r = i / EB, k = i % EB;
        se[r][k] = (rbase + r < nrows) ? emb[(size_t)(rbase + r) * EB + k] : 0.f;
    }
    __syncthreads();

    int f = threadIdx.x;  // 0..127
    for (int q = 0; q < 4; ++q) {
        int n = q * 128 + f;
        float acc[RPB];
        float c0 = isLen ? g_c[n] : 0.f;   // fold bias into len table only
#pragma unroll
        for (int r = 0; r < RPB; ++r) acc[r] = c0;
        const float* wr = g_Wc + n * RNNIN + koff;
        for (int k = 0; k < EB; ++k) {
            float w = wr[k];
#pragma unroll
            for (int r = 0; r < RPB; ++r) acc[r] += w * se[r][k];
        }
        for (int r = 0; r < RPB; ++r)
            if (rbase + r < nrows) dst[(size_t)(rbase + r) * H_ + n] = acc[r];
    }
}

// ---------------- kernel C: transpose h2h_w -> fp16 [k][n] ----------------
__global__ void k_wt(const float* __restrict__ h2h_w) {
    int k = blockIdx.x, n = threadIdx.x;
    g_W16t[k * H_ + n] = __float2half(h2h_w[n * H_ + k]);
}

// ---------------- kernel D: the recurrence ----------------
__device__ __forceinline__ void cpa16(void* s, const void* g) {
    unsigned sa = (unsigned)__cvta_generic_to_shared(s);
    asm volatile("cp.async.cg.shared.global [%0], [%1], 16;" :: "r"(sa), "l"(g));
}

__global__ void __cluster_dims__(4, 1, 1) __launch_bounds__(256, 1)
k_rnn(const int* __restrict__ x) {
    extern __shared__ __half smem[];
    __half* sW  = smem;                               // [512][LDW]
    __half* sH  = smem + H_ * LDW;                    // [MB][LDH]
    float*  sAcc = (float*)(sH + MB * LDH);           // [MB][LDA]

    int rank   = blockIdx.x & 3;
    int cid    = blockIdx.x >> 2;
    int batch0 = cid * MB;
    int n0     = rank * NN;
    int tid    = threadIdx.x;

    // resident W slice: 512 rows x 128 halves (16 chunks of 16B per row)
    for (int i = tid; i < H_ * 16; i += 256) {
        int k = i >> 4, c = i & 15;
        cpa16(sW + k * LDW + c * 8, g_W16t + (size_t)k * H_ + n0 + c * 8);
    }
    asm volatile("cp.async.commit_group;");

    int warp = tid >> 5;
    int mi   = warp & 1;     // m tile (2 x 16)
    int nb   = warp >> 1;    // n group (4 x 32)

    for (int t = 0; t < T_; ++t) {
        int rb = t & 1, wb = rb ^ 1;
        if (t == 0) {
            for (int i = tid; i < MB * LDH / 2; i += 256) ((int*)sH)[i] = 0;
        } else {
            for (int i = tid; i < MB * 64; i += 256) {
                int r = i >> 6, c = i & 63;
                cpa16(sH + r * LDH + c * 8, &g_h16[rb][(size_t)(batch0 + r) * H_ + c * 8]);
            }
            asm volatile("cp.async.commit_group;");
        }
        asm volatile("cp.async.wait_group 0;");
        __syncthreads();

        // [32 x 512] @ [512 x 128] -> [32 x 128], each warp a [16 x 32] tile
        wmma::fragment<wmma::accumulator, 16, 16, 16, float> acc0, acc1;
        wmma::fill_fragment(acc0, 0.f);
        wmma::fill_fragment(acc1, 0.f);
#pragma unroll 4
        for (int kk = 0; kk < H_ / 16; ++kk) {
            wmma::fragment<wmma::matrix_a, 16, 16, 16, __half, wmma::row_major> a;
            wmma::fragment<wmma::matrix_b, 16, 16, 16, __half, wmma::row_major> b0, b1;
            wmma::load_matrix_sync(a,  sH + mi * 16 * LDH + kk * 16, LDH);
            wmma::load_matrix_sync(b0, sW + kk * 16 * LDW + nb * 32, LDW);
            wmma::load_matrix_sync(b1, sW + kk * 16 * LDW + nb * 32 + 16, LDW);
            wmma::mma_sync(acc0, a, b0, acc0);
            wmma::mma_sync(acc1, a, b1, acc1);
        }
        wmma::store_matrix_sync(sAcc + mi * 16 * LDA + nb * 32,      acc0, LDA, wmma::mem_row_major);
        wmma::store_matrix_sync(sAcc + mi * 16 * LDA + nb * 32 + 16, acc1, LDA, wmma::mem_row_major);
        __syncthreads();

        // epilogue: + A_len[idx0] + A_ipd[idx1] (bias folded), tanh, emit fp16 state
        int r  = tid >> 3, cg = tid & 7;
        int nl = cg * 16;
        int b  = batch0 + r;
        const int* xp = x + ((size_t)b * T_ + t) * 2;
        int i0 = xp[0], i1 = xp[1];
        const float4* pa = (const float4*)(g_Alen + (size_t)i0 * H_ + n0 + nl);
        const float4* pb = (const float4*)(g_Aipd + (size_t)i1 * H_ + n0 + nl);
        const float4* pq = (const float4*)(sAcc + r * LDA + nl);
        __half2 hv[8];
        float4  fres[4];
#pragma unroll
        for (int j = 0; j < 4; ++j) {
            float4 qa = pq[j], va = pa[j], vb = pb[j];
            float4 o;
            o.x = tanhf(qa.x + va.x + vb.x);
            o.y = tanhf(qa.y + va.y + vb.y);
            o.z = tanhf(qa.z + va.z + vb.z);
            o.w = tanhf(qa.w + va.w + vb.w);
            fres[j] = o;
            hv[j * 2]     = __floats2half2_rn(o.x, o.y);
            hv[j * 2 + 1] = __floats2half2_rn(o.z, o.w);
        }
        uint4* dsth = (uint4*)(&g_h16[wb][(size_t)b * H_ + n0 + nl]);
        dsth[0] = ((uint4*)hv)[0];
        dsth[1] = ((uint4*)hv)[1];
        if (t == T_ - 1) {
            float4* dl = (float4*)(g_hlast + (size_t)b * H_ + n0 + nl);
#pragma unroll
            for (int j = 0; j < 4; ++j) dl[j] = fres[j];
        }

        // cluster-wide step barrier: arrive=release, wait=acquire (orders the
        // g_h16 stores against peers' next-step cp.async.cg loads, which bypass L1)
        asm volatile("barrier.cluster.arrive.aligned;" ::: "memory");
        asm volatile("barrier.cluster.wait.aligned;"   ::: "memory");
    }
}

// ---------------- kernel E: fc2 ----------------
__global__ void k_fc2(const float* __restrict__ fc2_w, const float* __restrict__ fc2_b,
                      float* __restrict__ out) {
    __shared__ float sh[16][H_];
    int batch0 = blockIdx.x * 16;
    for (int i = threadIdx.x; i < 16 * H_; i += 256) {
        int r = i >> 9, k = i & (H_ - 1);
        sh[r][k] = g_hlast[(size_t)(batch0 + r) * H_ + k];
    }
    __syncthreads();
    int tid = threadIdx.x;
    if (tid < 200) {
        int l = tid % 100, bh = tid / 100;
        float acc[8];
        float bias = fc2_b[l];
#pragma unroll
        for (int i = 0; i < 8; ++i) acc[i] = bias;
        const float4* wr = (const float4*)(fc2_w + (size_t)l * H_);
        for (int k4 = 0; k4 < H_ / 4; ++k4) {
            float4 w = wr[k4];
#pragma unroll
            for (int i = 0; i < 8; ++i) {
                float4 h = *(const float4*)(&sh[bh * 8 + i][k4 * 4]);
                acc[i] += w.x * h.x + w.y * h.y + w.z * h.z + w.w * h.w;
            }
        }
        for (int i = 0; i < 8; ++i)
            out[(size_t)(batch0 + bh * 8 + i) * LAB + l] = acc[i];
    }
}

// ---------------- launch ----------------
extern "C" void kernel_launch(void* const* d_in, const int* in_sizes, int n_in,
                              void* d_out, int out_size) {
    const int* x            = (const int*)d_in[0];
    const float* len_emb    = (const float*)d_in[1];
    const float* ipd_emb    = (const float*)d_in[2];
    const float* fc1_w      = (const float*)d_in[3];
    const float* fc1_b      = (const float*)d_in[4];
    const float* x2h_w      = (const float*)d_in[5];
    const float* x2h_b      = (const float*)d_in[6];
    const float* h2h_w      = (const float*)d_in[7];
    const float* h2h_b      = (const float*)d_in[8];
    const float* fc2_w      = (const float*)d_in[9];
    const float* fc2_b      = (const float*)d_in[10];
    float* out = (float*)d_out;

    cudaFuncSetAttribute(k_rnn, cudaFuncAttributeMaxDynamicSharedMemorySize, SMEM_BYTES);

    k_prep  <<<512, 128>>>(fc1_w, fc1_b, x2h_w, x2h_b, h2h_b);
    k_tables<<<(LENV + RPB - 1) / RPB + IPDV / RPB, 128>>>(len_emb, ipd_emb);
    k_wt    <<<512, 512>>>(h2h_w);
    k_rnn   <<<128, 256, SMEM_BYTES>>>(x);
    k_fc2   <<<B_ / 16, 256>>>(fc2_w, fc2_b, out);
}

// round 3
// speedup vs baseline: 1.0033x; 1.0033x over previous
#include <cuda_runtime.h>
#include <cuda_fp16.h>
#include <mma.h>

using namespace nvcuda;

#define B_    1024
#define T_    128
#define H_    512
#define RNNIN 128
#define LENV  1500
#define IPDV  256
#define EB    64
#define LAB   100

// recurrence tiling
#define MB   32      // batch rows per cluster
#define NN   128     // hidden slice per CTA
#define LDW  136     // sW row pitch (halves)
#define LDH  520     // sH row pitch (halves)
#define LDA  132     // sAcc row pitch (floats)
#define SMEM_BYTES (H_*LDW*2 + MB*LDH*2 + MB*LDA*4)   // 139264+33280+16896 = 189440

// ---------------- device scratch (static: no allocation allowed) ----------------
__device__ float  g_Wc[H_ * RNNIN];         // x2h_w @ fc1_w  [512,128]
__device__ float  g_c[H_];                  // folded bias (x2h_w@fc1_b + x2h_b + h2h_b)
__device__ float  g_Alen[LENV * H_];        // fused len table [1500,512] (includes g_c)
__device__ float  g_Aipd[IPDV * H_];        // fused ipd table [256,512]
__device__ __half g_W16t[H_ * H_];          // h2h_w transposed to [k][n], fp16
__device__ __half g_h16[2][B_ * H_];        // double-buffered recurrent state (fp16)
__device__ float  g_hlast[B_ * H_];         // final state in fp32 for fc2

// ---------------- kernel A: Wc = x2h_w @ fc1_w ; folded bias ----------------
__global__ void k_prep(const float* __restrict__ fc1_w, const float* __restrict__ fc1_b,
                       const float* __restrict__ x2h_w, const float* __restrict__ x2h_b,
                       const float* __restrict__ h2h_b) {
    __shared__ float s[RNNIN];
    int n = blockIdx.x;          // 0..511
    int f = threadIdx.x;         // 0..127
    s[f] = x2h_w[n * RNNIN + f];
    __syncthreads();
    float acc = 0.f;
#pragma unroll 4
    for (int j = 0; j < RNNIN; ++j) acc += s[j] * fc1_w[j * 128 + f];
    g_Wc[n * RNNIN + f] = acc;
    if (f == 0) {
        float cb = x2h_b[n] + h2h_b[n];
        for (int j = 0; j < RNNIN; ++j) cb += s[j] * fc1_b[j];
        g_c[n] = cb;
    }
}

// ---------------- kernel B: fused embedding tables ----------------
#define RPB 16
__global__ void k_tables(const float* __restrict__ len_emb, const float* __restrict__ ipd_emb) {
    __shared__ float se[RPB][EB];
    int bid = blockIdx.x;
    const int lenBlocks = (LENV + RPB - 1) / RPB;   // 94
    bool isLen = bid < lenBlocks;
    int rbase, nrows, koff;
    const float* emb;
    float* dst;
    if (isLen) { rbase = bid * RPB;              nrows = LENV; koff = 0;  emb = len_emb; dst = g_Alen; }
    else       { rbase = (bid - lenBlocks) * RPB; nrows = IPDV; koff = EB; emb = ipd_emb; dst = g_Aipd; }

    for (int i = threadIdx.x; i < RPB * EB; i += blockDim.x) {
        int r = i / EB, k = i % EB;
        se[r][k] = (rbase + r < nrows) ? emb[(size_t)(rbase + r) * EB + k] : 0.f;
    }
    __syncthreads();

    int f = threadIdx.x;  // 0..127
    for (int q = 0; q < 4; ++q) {
        int n = q * 128 + f;
        float acc[RPB];
        float c0 = isLen ? g_c[n] : 0.f;   // fold bias into len table only
#pragma unroll
        for (int r = 0; r < RPB; ++r) acc[r] = c0;
        const float* wr = g_Wc + n * RNNIN + koff;
        for (int k = 0; k < EB; ++k) {
            float w = wr[k];
#pragma unroll
            for (int r = 0; r < RPB; ++r) acc[r] += w * se[r][k];
        }
        for (int r = 0; r < RPB; ++r)
            if (rbase + r < nrows) dst[(size_t)(rbase + r) * H_ + n] = acc[r];
    }
}

// ---------------- kernel C: transpose h2h_w -> fp16 [k][n] ----------------
__global__ void k_wt(const float* __restrict__ h2h_w) {
    int k = blockIdx.x, n = threadIdx.x;
    g_W16t[k * H_ + n] = __float2half(h2h_w[n * H_ + k]);
}

// ---------------- kernel D: the recurrence ----------------
__device__ __forceinline__ void cpa16(void* s, const void* g) {
    unsigned sa = (unsigned)__cvta_generic_to_shared(s);
    asm volatile("cp.async.cg.shared.global [%0], [%1], 16;" :: "r"(sa), "l"(g));
}

__global__ void __cluster_dims__(4, 1, 1) __launch_bounds__(256, 1)
k_rnn(const int* __restrict__ x) {
    extern __shared__ __half smem[];
    __half* sW  = smem;                               // [512][LDW]
    __half* sH  = smem + H_ * LDW;                    // [MB][LDH]
    float*  sAcc = (float*)(sH + MB * LDH);           // [MB][LDA]

    int rank   = blockIdx.x & 3;
    int cid    = blockIdx.x >> 2;
    int batch0 = cid * MB;
    int n0     = rank * NN;
    int tid    = threadIdx.x;

    // resident W slice: 512 rows x 128 halves (16 chunks of 16B per row)
    for (int i = tid; i < H_ * 16; i += 256) {
        int k = i >> 4, c = i & 15;
        cpa16(sW + k * LDW + c * 8, g_W16t + (size_t)k * H_ + n0 + c * 8);
    }
    asm volatile("cp.async.commit_group;");

    int warp = tid >> 5;
    int mi   = warp & 1;     // m tile (2 x 16)
    int nb   = warp >> 1;    // n group (4 x 32)

    for (int t = 0; t < T_; ++t) {
        int rb = t & 1, wb = rb ^ 1;
        if (t == 0) {
            for (int i = tid; i < MB * LDH / 2; i += 256) ((int*)sH)[i] = 0;
        } else {
            for (int i = tid; i < MB * 64; i += 256) {
                int r = i >> 6, c = i & 63;
                cpa16(sH + r * LDH + c * 8, &g_h16[rb][(size_t)(batch0 + r) * H_ + c * 8]);
            }
            asm volatile("cp.async.commit_group;");
        }
        asm volatile("cp.async.wait_group 0;");
        __syncthreads();

        // [32 x 512] @ [512 x 128] -> [32 x 128], each warp a [16 x 32] tile
        wmma::fragment<wmma::accumulator, 16, 16, 16, float> acc0, acc1;
        wmma::fill_fragment(acc0, 0.f);
        wmma::fill_fragment(acc1, 0.f);
#pragma unroll 4
        for (int kk = 0; kk < H_ / 16; ++kk) {
            wmma::fragment<wmma::matrix_a, 16, 16, 16, __half, wmma::row_major> a;
            wmma::fragment<wmma::matrix_b, 16, 16, 16, __half, wmma::row_major> b0, b1;
            wmma::load_matrix_sync(a,  sH + mi * 16 * LDH + kk * 16, LDH);
            wmma::load_matrix_sync(b0, sW + kk * 16 * LDW + nb * 32, LDW);
            wmma::load_matrix_sync(b1, sW + kk * 16 * LDW + nb * 32 + 16, LDW);
            wmma::mma_sync(acc0, a, b0, acc0);
            wmma::mma_sync(acc1, a, b1, acc1);
        }
        wmma::store_matrix_sync(sAcc + mi * 16 * LDA + nb * 32,      acc0, LDA, wmma::mem_row_major);
        wmma::store_matrix_sync(sAcc + mi * 16 * LDA + nb * 32 + 16, acc1, LDA, wmma::mem_row_major);
        __syncthreads();

        // epilogue: + A_len[idx0] + A_ipd[idx1] (bias folded), tanh, emit fp16 state
        int r  = tid >> 3, cg = tid & 7;
        int nl = cg * 16;
        int b  = batch0 + r;
        const int* xp = x + ((size_t)b * T_ + t) * 2;
        int i0 = xp[0], i1 = xp[1];
        const float4* pa = (const float4*)(g_Alen + (size_t)i0 * H_ + n0 + nl);
        const float4* pb = (const float4*)(g_Aipd + (size_t)i1 * H_ + n0 + nl);
        const float4* pq = (const float4*)(sAcc + r * LDA + nl);
        __half2 hv[8];
        float4  fres[4];
#pragma unroll
        for (int j = 0; j < 4; ++j) {
            float4 qa = pq[j], va = pa[j], vb = pb[j];
            float4 o;
            o.x = tanhf(qa.x + va.x + vb.x);
            o.y = tanhf(qa.y + va.y + vb.y);
            o.z = tanhf(qa.z + va.z + vb.z);
            o.w = tanhf(qa.w + va.w + vb.w);
            fres[j] = o;
            hv[j * 2]     = __floats2half2_rn(o.x, o.y);
            hv[j * 2 + 1] = __floats2half2_rn(o.z, o.w);
        }
        uint4* dsth = (uint4*)(&g_h16[wb][(size_t)b * H_ + n0 + nl]);
        dsth[0] = ((uint4*)hv)[0];
        dsth[1] = ((uint4*)hv)[1];
        if (t == T_ - 1) {
            float4* dl = (float4*)(g_hlast + (size_t)b * H_ + n0 + nl);
#pragma unroll
            for (int j = 0; j < 4; ++j) dl[j] = fres[j];
        }

        // cluster-wide step barrier: arrive=release, wait=acquire (orders the
        // g_h16 stores against peers' next-step cp.async.cg loads, which bypass L1)
        asm volatile("barrier.cluster.arrive.aligned;" ::: "memory");
        asm volatile("barrier.cluster.wait.aligned;"   ::: "memory");
    }
}

// ---------------- kernel E: fc2 ----------------
__global__ void k_fc2(const float* __restrict__ fc2_w, const float* __restrict__ fc2_b,
                      float* __restrict__ out) {
    __shared__ float sh[16][H_];
    int batch0 = blockIdx.x * 16;
    for (int i = threadIdx.x; i < 16 * H_; i += 256) {
        int r = i >> 9, k = i & (H_ - 1);
        sh[r][k] = g_hlast[(size_t)(batch0 + r) * H_ + k];
    }
    __syncthreads();
    int tid = threadIdx.x;
    if (tid < 200) {
        int l = tid % 100, bh = tid / 100;
        float acc[8];
        float bias = fc2_b[l];
#pragma unroll
        for (int i = 0; i < 8; ++i) acc[i] = bias;
        const float4* wr = (const float4*)(fc2_w + (size_t)l * H_);
        for (int k4 = 0; k4 < H_ / 4; ++k4) {
            float4 w = wr[k4];
#pragma unroll
            for (int i = 0; i < 8; ++i) {
                float4 h = *(const float4*)(&sh[bh * 8 + i][k4 * 4]);
                acc[i] += w.x * h.x + w.y * h.y + w.z * h.z + w.w * h.w;
            }
        }
        for (int i = 0; i < 8; ++i)
            out[(size_t)(batch0 + bh * 8 + i) * LAB + l] = acc[i];
    }
}

// ---------------- launch ----------------
extern "C" void kernel_launch(void* const* d_in, const int* in_sizes, int n_in,
                              void* d_out, int out_size) {
    const int* x            = (const int*)d_in[0];
    const float* len_emb    = (const float*)d_in[1];
    const float* ipd_emb    = (const float*)d_in[2];
    const float* fc1_w      = (const float*)d_in[3];
    const float* fc1_b      = (const float*)d_in[4];
    const float* x2h_w      = (const float*)d_in[5];
    const float* x2h_b      = (const float*)d_in[6];
    const float* h2h_w      = (const float*)d_in[7];
    const float* h2h_b      = (const float*)d_in[8];
    const float* fc2_w      = (const float*)d_in[9];
    const float* fc2_b      = (const float*)d_in[10];
    float* out = (float*)d_out;

    cudaFuncSetAttribute(k_rnn, cudaFuncAttributeMaxDynamicSharedMemorySize, SMEM_BYTES);

    k_prep  <<<512, 128>>>(fc1_w, fc1_b, x2h_w, x2h_b, h2h_b);
    k_tables<<<(LENV + RPB - 1) / RPB + IPDV / RPB, 128>>>(len_emb, ipd_emb);
    k_wt    <<<512, 512>>>(h2h_w);
    k_rnn   <<<128, 256, SMEM_BYTES>>>(x);
    k_fc2   <<<B_ / 16, 256>>>(fc2_w, fc2_b, out);
}